// round 3
// baseline (speedup 1.0000x reference)
#include <cuda_runtime.h>
#include <cuda_bf16.h>
#include <cstdint>
#include <cstdio>

// Problem dims (fixed): T=2048, B=8, D=1024
#define TT 2048
#define BB 8
#define DD 1024
#define MROWS (TT*BB)          // 16384

// ---------------------------------------------------------------------------
// Scratch (device globals; no allocation allowed)
// ---------------------------------------------------------------------------
__device__ float g_h   [(size_t)MROWS * DD];        // layernorm(data), tf32-rounded
__device__ float g_qkv [(size_t)MROWS * 3 * DD];    // qkv projection
__device__ float g_x12 [(size_t)MROWS * 2 * DD];    // fc1 output
__device__ float g_W   [(size_t)TT * TT];           // exp(pos_bias), tf32-rounded
__device__ float g_XT  [(size_t)2 * BB * DD * TT];  // [16384, 2048]: rows 0..8191 = ek*v (n=b*D+d), 8192.. = ek
__device__ float g_Y   [(size_t)TT * 2 * BB * DD];  // [2048, 16384]: cols 0..8191 = num, 8192.. = den
__device__ float g_act [(size_t)MROWS * DD];        // sigmoid(q)*num/den, tf32-rounded
__device__ float g_gate[(size_t)MROWS * DD];        // x1*mish(gate), tf32-rounded
__device__ float g_w1  [(size_t)3*DD*DD];           // tf32-rounded qkv_w
__device__ float g_w2  [(size_t)2*DD*DD];           // tf32-rounded fc1_w
__device__ float g_w3  [(size_t)DD*DD];             // tf32-rounded out_w
__device__ float g_w4  [(size_t)DD*DD];             // tf32-rounded fc2_w

// ---------------------------------------------------------------------------
// Helpers
// ---------------------------------------------------------------------------
__device__ __forceinline__ float to_tf32(float x) {
    float r;
    asm("cvt.rna.tf32.f32 %0, %1;" : "=f"(r) : "f"(x));
    return r;
}

__device__ __forceinline__ void cp_async16(uint32_t saddr, const void* gptr) {
    asm volatile("cp.async.cg.shared.global [%0], [%1], 16;\n" :: "r"(saddr), "l"(gptr));
}
__device__ __forceinline__ void cp_commit() {
    asm volatile("cp.async.commit_group;\n");
}

// ---------------------------------------------------------------------------
// Elementwise kernels
// ---------------------------------------------------------------------------
__global__ void round_tf32_k(const float* __restrict__ src, float* __restrict__ dst, int n) {
    int i = blockIdx.x * blockDim.x + threadIdx.x;
    if (i < n) dst[i] = to_tf32(src[i]);
}

__global__ void expw_k(const float* __restrict__ pb, float* __restrict__ w, int n) {
    int i = blockIdx.x * blockDim.x + threadIdx.x;
    if (i < n) w[i] = to_tf32(expf(pb[i]));
}

// LayerNorm over last dim (D=1024); one block (256 thr, float4) per row.
__global__ void ln_k(const float* __restrict__ x, float* __restrict__ h) {
    __shared__ float red[16];
    const size_t row = blockIdx.x;
    const float4* xr = (const float4*)(x + row * DD);
    float4 v = xr[threadIdx.x];
    float s = v.x + v.y + v.z + v.w;
    float q = v.x*v.x + v.y*v.y + v.z*v.z + v.w*v.w;
    #pragma unroll
    for (int o = 16; o; o >>= 1) {
        s += __shfl_xor_sync(0xffffffffu, s, o);
        q += __shfl_xor_sync(0xffffffffu, q, o);
    }
    int wid = threadIdx.x >> 5;
    if ((threadIdx.x & 31) == 0) { red[wid] = s; red[8 + wid] = q; }
    __syncthreads();
    s = 0.f; q = 0.f;
    #pragma unroll
    for (int i = 0; i < 8; i++) { s += red[i]; q += red[8 + i]; }
    float mean = s * (1.0f / DD);
    float var  = fmaxf(q * (1.0f / DD) - mean * mean, 0.0f);
    float rs   = rsqrtf(var + 1.17549435e-38f);
    float4 o;
    o.x = to_tf32((v.x - mean) * rs);
    o.y = to_tf32((v.y - mean) * rs);
    o.z = to_tf32((v.z - mean) * rs);
    o.w = to_tf32((v.w - mean) * rs);
    ((float4*)(h + row * DD))[threadIdx.x] = o;
}

// Build XT[n, j]: n = b*D+d (rows 0..8191: ek*v, rows 8192..: ek), j = time index.
// Reads qkv rows (j*B+b), k at col D+d, v at col 2D+d. 32x32 transpose tiles.
__global__ void make_xt_k(const float* __restrict__ qkv, float* __restrict__ XT) {
    __shared__ float s_ekv[32][33];
    __shared__ float s_ek [32][33];
    const int d0 = blockIdx.x * 32;
    const int j0 = blockIdx.y * 32;
    const int b  = blockIdx.z;
    const int x  = threadIdx.x;  // 0..31
    #pragma unroll
    for (int i = 0; i < 4; i++) {
        int j = threadIdx.y + i * 8;
        const float* row = qkv + ((size_t)(j0 + j) * BB + b) * (3 * DD);
        float kk = row[DD + d0 + x];
        float vv = row[2 * DD + d0 + x];
        float ek = expf(kk);
        s_ek[j][x]  = ek;
        s_ekv[j][x] = ek * vv;
    }
    __syncthreads();
    #pragma unroll
    for (int i = 0; i < 4; i++) {
        int d = threadIdx.y + i * 8;
        size_t n = (size_t)b * DD + d0 + d;
        XT[n * TT + j0 + x]                        = to_tf32(s_ekv[x][d]);
        XT[(n + (size_t)BB * DD) * TT + j0 + x]    = to_tf32(s_ek[x][d]);
    }
}

// act = tf32( sigmoid(q) * num/den ), layout [MROWS, D]
__global__ void act_k(const float* __restrict__ qkv, const float* __restrict__ Y,
                      float* __restrict__ out) {
    size_t idx = (size_t)blockIdx.x * blockDim.x + threadIdx.x;  // < 16M
    int m = (int)(idx >> 10);
    int d = (int)(idx & 1023);
    int t = m >> 3;
    int b = m & 7;
    float q = qkv[(size_t)m * (3 * DD) + d];
    size_t yb = (size_t)t * (2 * BB * DD) + (size_t)b * DD + d;
    float num = Y[yb];
    float den = Y[yb + (size_t)BB * DD];
    float sg = 1.0f / (1.0f + expf(-q));
    out[idx] = to_tf32(sg * (num / den));
}

// g = tf32( x1 * mish(gate) ), mish(x) = x * tanh(softplus(x))
__global__ void swiglu_k(const float* __restrict__ x12, float* __restrict__ out) {
    size_t idx = (size_t)blockIdx.x * blockDim.x + threadIdx.x;
    int m = (int)(idx >> 10);
    int d = (int)(idx & 1023);
    const float* r = x12 + (size_t)m * (2 * DD);
    float x1 = r[d];
    float gt = r[DD + d];
    float sp = (gt > 20.0f) ? gt : log1pf(expf(gt));
    out[idx] = to_tf32(x1 * gt * tanhf(sp));
}

// ---------------------------------------------------------------------------
// GEMM (TN): C[M,N] = A[M,K] * B[N,K]^T  (+ bias[n]) (+ aux[m,n])
// tf32 mma.sync m16n8k8, 128x128x32 block tile, 8 warps (64x32 warp tiles),
// cp.async double-buffered smem, stride-36 padding (conflict-free frag loads).
// ---------------------------------------------------------------------------
#define BM 128
#define BN 128
#define BK 32
#define STR 36
#define TILE_F (BM * STR)                  // floats per buffer per matrix
#define SMEM_BYTES (4 * TILE_F * 4)        // A(2 buf) + B(2 buf)

template<bool HAS_BIAS, bool HAS_AUX>
__global__ void __launch_bounds__(256) gemm_tn(
    const float* __restrict__ A, const float* __restrict__ B,
    const float* __restrict__ bias, const float* __restrict__ aux,
    float* __restrict__ C, int M, int N, int K)
{
    extern __shared__ float sm[];
    float* As = sm;                  // [2][BM][STR]
    float* Bs = sm + 2 * TILE_F;     // [2][BN][STR]

    const int tid = threadIdx.x;
    const size_t m0 = (size_t)blockIdx.y * BM;
    const size_t n0 = (size_t)blockIdx.x * BN;

    // global->smem load mapping: per matrix 1024 float4, 4 per thread
    const int lr = tid >> 3;   // 0..31 (row, +32*i)
    const int lc = tid & 7;    // float4 column
    const float* gA = A + (m0 + lr) * (size_t)K + lc * 4;
    const float* gB = B + (n0 + lr) * (size_t)K + lc * 4;
    const uint32_t sAa = (uint32_t)__cvta_generic_to_shared(&As[lr * STR + lc * 4]);
    const uint32_t sBa = (uint32_t)__cvta_generic_to_shared(&Bs[lr * STR + lc * 4]);

    const int warp = tid >> 5, lane = tid & 31;
    const int g = lane >> 2, tg = lane & 3;
    const int wm = (warp >> 2) * 64;   // 0 or 64
    const int wn = (warp & 3) * 32;    // 0,32,64,96

    float c[4][4][4];
    #pragma unroll
    for (int i = 0; i < 4; i++)
        #pragma unroll
        for (int j = 0; j < 4; j++)
            #pragma unroll
            for (int e = 0; e < 4; e++) c[i][j][e] = 0.0f;

    const int nk = K / BK;

    // prefetch tile 0 -> buf 0
    {
        #pragma unroll
        for (int i = 0; i < 4; i++) {
            cp_async16(sAa + i * 32 * STR * 4, gA + (size_t)(32 * i) * K);
            cp_async16(sBa + i * 32 * STR * 4, gB + (size_t)(32 * i) * K);
        }
        cp_commit();
    }

    for (int kt = 0; kt < nk; kt++) {
        const int cur = kt & 1;
        if (kt + 1 < nk) {
            const float* a = gA + (size_t)(kt + 1) * BK;
            const float* b = gB + (size_t)(kt + 1) * BK;
            const uint32_t da = sAa + (cur ^ 1) * TILE_F * 4;
            const uint32_t db = sBa + (cur ^ 1) * TILE_F * 4;
            #pragma unroll
            for (int i = 0; i < 4; i++) {
                cp_async16(da + i * 32 * STR * 4, a + (size_t)(32 * i) * K);
                cp_async16(db + i * 32 * STR * 4, b + (size_t)(32 * i) * K);
            }
            cp_commit();
            asm volatile("cp.async.wait_group 1;\n");
        } else {
            asm volatile("cp.async.wait_group 0;\n");
        }
        __syncthreads();

        const float* Ab = As + cur * TILE_F;
        const float* Bb = Bs + cur * TILE_F;
        #pragma unroll
        for (int ks = 0; ks < 4; ks++) {
            const int k = ks * 8;
            uint32_t af[4][4], bf[4][2];
            #pragma unroll
            for (int mt = 0; mt < 4; mt++) {
                const uint32_t* p = (const uint32_t*)(Ab + (wm + mt * 16 + g) * STR + k + tg);
                af[mt][0] = p[0];
                af[mt][1] = p[8 * STR];
                af[mt][2] = p[4];
                af[mt][3] = p[8 * STR + 4];
            }
            #pragma unroll
            for (int nt = 0; nt < 4; nt++) {
                const uint32_t* p = (const uint32_t*)(Bb + (wn + nt * 8 + g) * STR + k + tg);
                bf[nt][0] = p[0];
                bf[nt][1] = p[4];
            }
            #pragma unroll
            for (int mt = 0; mt < 4; mt++)
                #pragma unroll
                for (int nt = 0; nt < 4; nt++) {
                    asm volatile(
                        "mma.sync.aligned.m16n8k8.row.col.f32.tf32.tf32.f32 "
                        "{%0,%1,%2,%3}, {%4,%5,%6,%7}, {%8,%9}, {%0,%1,%2,%3};\n"
                        : "+f"(c[mt][nt][0]), "+f"(c[mt][nt][1]),
                          "+f"(c[mt][nt][2]), "+f"(c[mt][nt][3])
                        : "r"(af[mt][0]), "r"(af[mt][1]), "r"(af[mt][2]), "r"(af[mt][3]),
                          "r"(bf[nt][0]), "r"(bf[nt][1]));
                }
        }
        __syncthreads();
    }

    // epilogue
    #pragma unroll
    for (int mt = 0; mt < 4; mt++) {
        const size_t r0 = m0 + wm + mt * 16 + g;
        const size_t r1 = r0 + 8;
        #pragma unroll
        for (int nt = 0; nt < 4; nt++) {
            const size_t col = n0 + wn + nt * 8 + tg * 2;
            float b0 = 0.f, b1 = 0.f;
            if (HAS_BIAS) { b0 = bias[col]; b1 = bias[col + 1]; }
            const size_t i0 = r0 * N + col;
            const size_t i1 = r1 * N + col;
            float v0 = c[mt][nt][0] + b0;
            float v1 = c[mt][nt][1] + b1;
            float v2 = c[mt][nt][2] + b0;
            float v3 = c[mt][nt][3] + b1;
            if (HAS_AUX) {
                v0 += aux[i0]; v1 += aux[i0 + 1];
                v2 += aux[i1]; v3 += aux[i1 + 1];
            }
            C[i0] = v0; C[i0 + 1] = v1;
            C[i1] = v2; C[i1 + 1] = v3;
        }
    }
}

// ---------------------------------------------------------------------------
// Host launch
// ---------------------------------------------------------------------------
extern "C" void kernel_launch(void* const* d_in, const int* in_sizes, int n_in,
                              void* d_out, int out_size) {
    const float* data  = (const float*)d_in[0];
    const float* qkv_w = (const float*)d_in[1];
    const float* qkv_b = (const float*)d_in[2];
    const float* pos_b = (const float*)d_in[3];
    const float* out_w = (const float*)d_in[4];
    const float* out_b = (const float*)d_in[5];
    const float* fc1_w = (const float*)d_in[6];
    const float* fc1_b = (const float*)d_in[7];
    const float* fc2_w = (const float*)d_in[8];
    const float* fc2_b = (const float*)d_in[9];
    float* out = (float*)d_out;

    float *h, *qkv, *x12, *W, *XT, *Y, *act, *gate, *w1, *w2, *w3, *w4;
    cudaGetSymbolAddress((void**)&h,    g_h);
    cudaGetSymbolAddress((void**)&qkv,  g_qkv);
    cudaGetSymbolAddress((void**)&x12,  g_x12);
    cudaGetSymbolAddress((void**)&W,    g_W);
    cudaGetSymbolAddress((void**)&XT,   g_XT);
    cudaGetSymbolAddress((void**)&Y,    g_Y);
    cudaGetSymbolAddress((void**)&act,  g_act);
    cudaGetSymbolAddress((void**)&gate, g_gate);
    cudaGetSymbolAddress((void**)&w1,   g_w1);
    cudaGetSymbolAddress((void**)&w2,   g_w2);
    cudaGetSymbolAddress((void**)&w3,   g_w3);
    cudaGetSymbolAddress((void**)&w4,   g_w4);

    cudaFuncSetAttribute(gemm_tn<true,  false>, cudaFuncAttributeMaxDynamicSharedMemorySize, SMEM_BYTES);
    cudaFuncSetAttribute(gemm_tn<false, false>, cudaFuncAttributeMaxDynamicSharedMemorySize, SMEM_BYTES);
    cudaFuncSetAttribute(gemm_tn<true,  true >, cudaFuncAttributeMaxDynamicSharedMemorySize, SMEM_BYTES);

    // tf32-round weights
    round_tf32_k<<<(3*DD*DD + 255)/256, 256>>>(qkv_w, w1, 3*DD*DD);
    round_tf32_k<<<(2*DD*DD + 255)/256, 256>>>(fc1_w, w2, 2*DD*DD);
    round_tf32_k<<<(DD*DD   + 255)/256, 256>>>(out_w, w3, DD*DD);
    round_tf32_k<<<(DD*DD   + 255)/256, 256>>>(fc2_w, w4, DD*DD);

    // layernorm (shared by both branches) and exp(pos_bias)
    ln_k<<<MROWS, 256>>>(data, h);
    expw_k<<<(TT*TT + 255)/256, 256>>>(pos_b, W, TT*TT);

    // qkv = h @ qkv_w^T + b     [16384, 3072]
    gemm_tn<true, false><<<dim3(3*DD/BN, MROWS/BM), 256, SMEM_BYTES>>>(
        h, w1, qkv_b, nullptr, qkv, MROWS, 3*DD, DD);
    // x12 = h @ fc1_w^T + b     [16384, 2048]
    gemm_tn<true, false><<<dim3(2*DD/BN, MROWS/BM), 256, SMEM_BYTES>>>(
        h, w2, fc1_b, nullptr, x12, MROWS, 2*DD, DD);

    // XT = [ek*v ; ek] transposed to [16384, 2048]
    make_xt_k<<<dim3(DD/32, TT/32, BB), dim3(32, 8)>>>(qkv, XT);

    // Y = W @ XT^T  -> [2048, 16384] (num | den)
    gemm_tn<false, false><<<dim3(2*BB*DD/BN, TT/BM), 256, SMEM_BYTES>>>(
        W, XT, nullptr, nullptr, Y, TT, 2*BB*DD, TT);

    // act = sigmoid(q) * num/den
    act_k<<<(MROWS*DD)/256, 256>>>(qkv, Y, act);

    // out = data + act @ out_w^T + out_b
    gemm_tn<true, true><<<dim3(DD/BN, MROWS/BM), 256, SMEM_BYTES>>>(
        act, w3, out_b, data, out, MROWS, DD, DD);

    // gate = x1 * mish(x2)
    swiglu_k<<<(MROWS*DD)/256, 256>>>(x12, gate);

    // out += gate @ fc2_w^T + fc2_b
    gemm_tn<true, true><<<dim3(DD/BN, MROWS/BM), 256, SMEM_BYTES>>>(
        gate, w4, fc2_b, out, out, MROWS, DD, DD);
}